// round 15
// baseline (speedup 1.0000x reference)
#include <cuda_runtime.h>
#include <cuda_bf16.h>

// Problem constants
#define T_ 64
#define S_ 32
#define F_ 256
#define A_ 64
#define P2_ 64   // 2*P
#define NQ_ 2048 // T*S

// Packed fp32x2 FMA (sm_100+): d = a * b + d, two lanes per instruction.
__device__ __forceinline__ void ffma2(unsigned long long& d,
                                      unsigned long long a,
                                      unsigned long long b) {
    asm("fma.rn.f32x2 %0, %1, %2, %0;" : "+l"(d) : "l"(a), "l"(b));
}
__device__ __forceinline__ unsigned long long pack2(float x) {
    unsigned long long r;
    asm("mov.b64 %0, {%1, %1};" : "=l"(r) : "f"(x));
    return r;
}
__device__ __forceinline__ float2 unpack2(unsigned long long d) {
    float2 u;
    asm("mov.b64 {%0, %1}, %2;" : "=f"(u.x), "=f"(u.y) : "l"(d));
    return u;
}

// Scratch (device globals; no allocations allowed)
__device__ float g_theta[NQ_ * A_];
__device__ float g_xphi[NQ_ * A_];
__device__ float g_xg[NQ_ * F_];
__device__ float g_thetaB[NQ_ * P2_];
__device__ float g_thetaD[NQ_ * 16];      // 10 used, padded
__device__ float g_pos[S_ * S_ * P2_];    // pos[sigma][k][p]
__device__ float g_ctxg[NQ_ * F_];        // spatial ctx_g
__device__ float g_ctxp[NQ_ * P2_];       // temporal: btmp + cd@Wtmp
__device__ float g_ctxp2[NQ_ * P2_];      // spatial ctx_p (separate: no race)
// g_A4[sigma][t][tau] : temporal attention matrix (K-major operand for k4b)
__device__ float g_A4[S_ * T_ * T_];

// k1 dynamic smem: Xs 32x132 + Ws 128x68
#define K1_XS 4224
#define K1_WS 8704
#define K1_SMEMF (K1_XS + K1_WS)
#define K1_SMEMB (K1_SMEMF * 4)   // 51712 bytes

// ---------------------------------------------------------------------------
// L1: seg 0..5 = projection GEMM x @ [Wa | WbX | WgX] (+thetaB/thetaD on seg0)
//     seg 6    = pos embedding (independent work, same launch)
// grid (64, 7), 128 threads. 32M x 64N tiles, 4x4 micro-tile (FFMA2 packed),
// K-chunks of 128 (2 chunks -> 4 barriers/block).
// ---------------------------------------------------------------------------
__global__ __launch_bounds__(128)
void k1_proj(const float* __restrict__ x,
             const float* __restrict__ Wa,
             const float* __restrict__ Wb,
             const float* __restrict__ Wg,
             const float* __restrict__ ba,
             const float* __restrict__ Wtmp,
             const float* __restrict__ positions,
             const float* __restrict__ Wpos,
             const float* __restrict__ bpos) {
    extern __shared__ float dsm[];
    float* Xs = dsm;             // [32][132]
    float* Ws = dsm + K1_XS;     // [128][68]
    const int tid = threadIdx.x;
    const int m0 = blockIdx.x * 32;
    const int seg = blockIdx.y;

    if (seg == 6) {
        int base = blockIdx.x * 1024;
        #pragma unroll
        for (int li = 0; li < 8; li++) {
            int idx = base + tid + li * 128;
            int p = idx & 63;
            int jk = idx >> 6;
            int half = p >> 5, pp = p & 31;
            const float* src = positions + half * (S_*S_*9) + jk * 9;
            float s = bpos[pp];
            #pragma unroll
            for (int d = 0; d < 9; d++) s += src[d] * Wpos[d * 32 + pp];
            g_pos[idx] = s;
        }
        return;
    }

    const float* W;
    float* out;
    int ldw, coloff, ldo;
    bool addb = false;
    if (seg == 0)      { W = Wa; ldw = 64;  coloff = 0;          out = g_theta; ldo = 64;  addb = true; }
    else if (seg == 1) { W = Wb; ldw = 64;  coloff = 0;          out = g_xphi;  ldo = 64; }
    else               { W = Wg; ldw = 256; coloff = (seg-2)*64; out = g_xg;    ldo = 256; }

    const int tcol = tid & 15, trow = tid >> 4;   // trow 0..7 -> 4 rows each
    unsigned long long acc01[4] = {}, acc23[4] = {};   // packed (f0,f1),(f2,f3)

    #pragma unroll
    for (int kc = 0; kc < 2; kc++) {
        int kk = kc * 128;
        #pragma unroll
        for (int li = 0; li < 8; li++) {          // X: 32x128 = 1024 float4
            int f = tid + li * 128;
            int r = f >> 5, c4 = (f & 31) << 2;
            float4 v = *reinterpret_cast<const float4*>(x + (m0 + r) * 256 + kk + c4);
            Xs[r * 132 + c4 + 0] = v.x; Xs[r * 132 + c4 + 1] = v.y;
            Xs[r * 132 + c4 + 2] = v.z; Xs[r * 132 + c4 + 3] = v.w;
        }
        #pragma unroll
        for (int li = 0; li < 16; li++) {         // W: 128x64 = 2048 float4
            int f = tid + li * 128;
            int r = f >> 4, c4 = (f & 15) << 2;
            float4 v = *reinterpret_cast<const float4*>(W + (kk + r) * ldw + coloff + c4);
            *reinterpret_cast<float4*>(&Ws[r * 68 + c4]) = v;
        }
        __syncthreads();
        #pragma unroll 16
        for (int k = 0; k < 128; k++) {
            ulonglong2 bb = *reinterpret_cast<const ulonglong2*>(&Ws[k * 68 + tcol * 4]);
            #pragma unroll
            for (int i = 0; i < 4; i++) {
                unsigned long long ap = pack2(Xs[(trow*4 + i) * 132 + k]);
                ffma2(acc01[i], ap, bb.x);
                ffma2(acc23[i], ap, bb.y);
            }
        }
        __syncthreads();
    }
    #pragma unroll
    for (int i = 0; i < 4; i++) {
        int r = trow*4 + i;
        float2 v01 = unpack2(acc01[i]);
        float2 v23 = unpack2(acc23[i]);
        float vres[4] = {v01.x, v01.y, v23.x, v23.y};
        #pragma unroll
        for (int j = 0; j < 4; j++) {
            int c = tcol*4 + j;
            float v = vres[j];
            if (addb) v += ba[c];
            out[(m0 + r) * ldo + coloff + c] = v;
            if (seg == 0) Xs[r * 132 + c] = v;
        }
    }
    if (seg != 0) return;

    // --- thetaB = theta @ WbP^T : WbP laid out as Ws[a][p] ---
    __syncthreads();
    #pragma unroll
    for (int li = 0; li < 32; li++) {
        int e = tid + li * 128;            // e = p*64 + a
        int p = e >> 6, a = e & 63;
        Ws[a * 68 + p] = Wb[(256 + p) * 64 + a];
    }
    __syncthreads();
    unsigned long long bacc01[4] = {}, bacc23[4] = {};
    #pragma unroll 16
    for (int a = 0; a < 64; a++) {
        ulonglong2 bb = *reinterpret_cast<const ulonglong2*>(&Ws[a * 68 + tcol * 4]);
        #pragma unroll
        for (int i = 0; i < 4; i++) {
            unsigned long long ap = pack2(Xs[(trow*4 + i) * 132 + a]);
            ffma2(bacc01[i], ap, bb.x);
            ffma2(bacc23[i], ap, bb.y);
        }
    }
    __syncthreads();
    #pragma unroll
    for (int i = 0; i < 4; i++) {
        int r = trow*4 + i;
        float2 v01 = unpack2(bacc01[i]);
        float2 v23 = unpack2(bacc23[i]);
        float vres[4] = {v01.x, v01.y, v23.x, v23.y};
        #pragma unroll
        for (int j = 0; j < 4; j++) {
            int p = tcol*4 + j;
            g_thetaB[(m0 + r) * 64 + p] = vres[j];
            Xs[r * 132 + p] = vres[j];
        }
    }
    __syncthreads();
    for (int e = tid; e < 320; e += 128) {
        int r = e / 10, d = e % 10;
        float s = 0.f;
        #pragma unroll
        for (int p = 0; p < 64; p++) s += Xs[r * 132 + p] * Wtmp[d * 64 + p];
        g_thetaD[(m0 + r) * 16 + d] = s;
    }
}

// ---------------------------------------------------------------------------
// L2: kbig. blocks 0..255 = temporal scores (writes g_A4, g_ctxp);
//          blocks 256..511 = spatial attention with inline posscore
//          (writes g_ctxg, g_ctxp2). Both depend only on L1.
// ---------------------------------------------------------------------------
__global__ __launch_bounds__(256)
void kbig(const float* __restrict__ temp,
          const float* __restrict__ Wtmp,
          const float* __restrict__ btmp) {
    __shared__ float sm[11560];
    int tid = threadIdx.x, lane = tid & 31, w = tid >> 5;

    if (blockIdx.x < 256) {
        // ---- temporal branch ----
        float* xphiT = sm;            // [a][t] 64*66 = 4224
        float* Th    = sm + 4224;     // 8*64
        float* Td    = sm + 4736;     // 8*16
        float* bsh   = sm + 4864;     // [t][tl] 64*8
        float* Wts   = sm + 5376;     // 640

        int sigma = blockIdx.x & 31;
        int tg8 = blockIdx.x >> 5;         // taus [tg8*8, tg8*8+8)
        int tau = tg8 * 8 + w;
        int t0 = lane * 2, t1 = t0 + 1;

        for (int e = tid; e < 1024; e += 256) {
            int t = e >> 4, c4 = (e & 15) << 2;
            float4 v = *reinterpret_cast<const float4*>(g_xphi + (t * 32 + sigma) * 64 + c4);
            xphiT[(c4 + 0) * 66 + t] = v.x;
            xphiT[(c4 + 1) * 66 + t] = v.y;
            xphiT[(c4 + 2) * 66 + t] = v.z;
            xphiT[(c4 + 3) * 66 + t] = v.w;
        }
        for (int e = tid; e < 512; e += 256) {
            int tl = e >> 6, a = e & 63;
            Th[e] = g_theta[((tg8 * 8 + tl) * 32 + sigma) * 64 + a];
        }
        if (tid < 128) {
            int tl = tid >> 4;
            Td[tid] = g_thetaD[((tg8 * 8 + tl) * 32 + sigma) * 16 + (tid & 15)];
        }
        for (int e = tid; e < 640; e += 256) Wts[e] = Wtmp[e];

        float tp0[10], tp1[10];
        {
            const float2* s0p = reinterpret_cast<const float2*>(
                temp + (((tau * 64 + t0) * 32) + sigma) * 10);
            const float2* s1p = reinterpret_cast<const float2*>(
                temp + (((tau * 64 + t1) * 32) + sigma) * 10);
            #pragma unroll
            for (int i = 0; i < 5; i++) {
                float2 v0 = s0p[i]; tp0[2*i] = v0.x; tp0[2*i+1] = v0.y;
                float2 v1 = s1p[i]; tp1[2*i] = v1.x; tp1[2*i+1] = v1.y;
            }
        }
        __syncthreads();

        float s0 = 0.f, s1 = 0.f;
        #pragma unroll 16
        for (int a = 0; a < 64; a++) {
            float th = Th[w * 64 + a];
            float2 xv = *reinterpret_cast<const float2*>(&xphiT[a * 66 + t0]);
            s0 += th * xv.x;
            s1 += th * xv.y;
        }
        #pragma unroll
        for (int d = 0; d < 10; d++) {
            float td = Td[w * 16 + d];
            s0 += td * tp0[d];
            s1 += td * tp1[d];
        }

        float m = fmaxf(s0, s1);
        #pragma unroll
        for (int o = 16; o; o >>= 1) m = fmaxf(m, __shfl_xor_sync(0xffffffffu, m, o));
        float e0 = __expf(s0 - m), e1 = __expf(s1 - m);
        float sum = e0 + e1;
        #pragma unroll
        for (int o = 16; o; o >>= 1) sum += __shfl_xor_sync(0xffffffffu, sum, o);
        float inv = 1.f / sum;
        float b0 = e0 * inv, b1 = e1 * inv;
        bsh[t0 * 8 + w] = b0;
        bsh[t1 * 8 + w] = b1;

        float cdv[10];
        #pragma unroll
        for (int d = 0; d < 10; d++) {
            float v = b0 * tp0[d] + b1 * tp1[d];
            #pragma unroll
            for (int o = 16; o; o >>= 1) v += __shfl_xor_sync(0xffffffffu, v, o);
            cdv[d] = v;
        }

        {
            int q = tau * 32 + sigma;
            int p0 = lane, p1 = lane + 32;
            float v0 = btmp[p0], v1 = btmp[p1];
            #pragma unroll
            for (int d = 0; d < 10; d++) {
                v0 += cdv[d] * Wts[d * 64 + p0];
                v1 += cdv[d] * Wts[d * 64 + p1];
            }
            g_ctxp[q * 64 + p0] = v0;
            g_ctxp[q * 64 + p1] = v1;
        }

        __syncthreads();
        {
            int t = tid >> 2, tlp = (tid & 3) * 2;
            float2 bv = *reinterpret_cast<const float2*>(&bsh[t * 8 + tlp]);
            *reinterpret_cast<float2*>(
                g_A4 + sigma * 4096 + t * 64 + tg8 * 8 + tlp) = bv;
        }
        return;
    }

    // ---- spatial branch (inline posscore) ----
    float* xphi_s = sm;           // 32*65 = 2080
    float* xg_s   = sm + 2080;    // 32*256 = 8192
    float* Th     = sm + 10272;   // 8*64
    float* TB     = sm + 10784;   // 8*64
    float* asc    = sm + 11296;   // 8*33

    int b3 = blockIdx.x - 256;
    int tau = b3 >> 2;
    int sq = b3 & 3;              // sigmas [sq*8, sq*8+8)

    for (int e = tid; e < 512; e += 256) {
        int k = e >> 4, c4 = (e & 15) << 2;
        float4 v = *reinterpret_cast<const float4*>(g_xphi + (tau * 32 + k) * 64 + c4);
        xphi_s[k * 65 + c4 + 0] = v.x; xphi_s[k * 65 + c4 + 1] = v.y;
        xphi_s[k * 65 + c4 + 2] = v.z; xphi_s[k * 65 + c4 + 3] = v.w;
    }
    for (int e = tid; e < 2048; e += 256) {
        int k = e >> 6, c4 = (e & 63) << 2;
        float4 v = *reinterpret_cast<const float4*>(g_xg + (tau * 32 + k) * 256 + c4);
        *reinterpret_cast<float4*>(&xg_s[k * 256 + c4]) = v;
    }
    for (int e = tid; e < 512; e += 256) {
        int sig = e >> 6, c = e & 63;
        Th[sig * 64 + c] = g_theta[(tau * 32 + sq * 8 + sig) * 64 + c];
        TB[sig * 64 + c] = g_thetaB[(tau * 32 + sq * 8 + sig) * 64 + c];
    }
    __syncthreads();

    {
        int sigma = sq * 8 + w;
        float s = 0.f;
        #pragma unroll
        for (int a = 0; a < 64; a++) s += Th[w * 64 + a] * xphi_s[lane * 65 + a];
        const float4* pp = reinterpret_cast<const float4*>(
            g_pos + sigma * 2048 + lane * 64);
        #pragma unroll
        for (int pg = 0; pg < 16; pg++) {
            float4 pv = pp[pg];
            s += TB[w * 64 + pg * 4 + 0] * pv.x + TB[w * 64 + pg * 4 + 1] * pv.y
               + TB[w * 64 + pg * 4 + 2] * pv.z + TB[w * 64 + pg * 4 + 3] * pv.w;
        }
        asc[w * 33 + lane] = s;
    }
    __syncwarp();

    {
        float s = asc[w * 33 + lane];
        float m = s;
        #pragma unroll
        for (int o = 16; o; o >>= 1) m = fmaxf(m, __shfl_xor_sync(0xffffffffu, m, o));
        float e = __expf(s - m);
        float sum = e;
        #pragma unroll
        for (int o = 16; o; o >>= 1) sum += __shfl_xor_sync(0xffffffffu, sum, o);
        asc[w * 33 + lane] = e / sum;
    }
    __syncwarp();

    {
        int sigma = sq * 8 + w;
        int q = tau * 32 + sigma;
        float4 acc0 = {0,0,0,0}, acc1 = {0,0,0,0};
        float cp0 = 0.f, cp1 = 0.f;
        const float* posb = g_pos + sigma * (32 * 64);
        #pragma unroll 4
        for (int k = 0; k < 32; k++) {
            float aw = asc[w * 33 + k];
            const float* xr = &xg_s[k * 256 + lane * 8];
            float4 x0 = *reinterpret_cast<const float4*>(xr + 0);
            float4 x1 = *reinterpret_cast<const float4*>(xr + 4);
            acc0.x += aw*x0.x; acc0.y += aw*x0.y; acc0.z += aw*x0.z; acc0.w += aw*x0.w;
            acc1.x += aw*x1.x; acc1.y += aw*x1.y; acc1.z += aw*x1.z; acc1.w += aw*x1.w;
            float2 pv = *reinterpret_cast<const float2*>(posb + k * 64 + lane * 2);
            cp0 += aw * pv.x; cp1 += aw * pv.y;
        }
        float* og = g_ctxg + q * 256 + lane * 8;
        *reinterpret_cast<float4*>(og + 0) = acc0;
        *reinterpret_cast<float4*>(og + 4) = acc1;
        float2 cpv; cpv.x = cp0; cpv.y = cp1;
        *reinterpret_cast<float2*>(g_ctxp2 + q * 64 + lane * 2) = cpv;
    }
}

// ---------------------------------------------------------------------------
// L3: out[tau,f] = [attn | ctxp+ctxp2]^T(64x128) @ [xg ; WgP](128x64)
//                  + ctxg + 2bg.
// grid 512 = (sigma 32, fc 4, tau-quarter 4); 128 threads; tile 16tau x 64f,
// 2x4 micro-tile, FFMA2 packed (A stride 20).
// ---------------------------------------------------------------------------
__global__ __launch_bounds__(128)
void k4b_out(const float* __restrict__ Wg,
             const float* __restrict__ bg,
             float* __restrict__ out) {
    __shared__ float As[64 * 20];   // [k][tau16], stride 20
    __shared__ float Bs[64 * 64];   // [k][f]
    int tid = threadIdx.x;
    int b = blockIdx.x;
    int sigma = b & 31;
    int fc = (b >> 5) & 3;
    int tq = b >> 7;                // tau quarter: taus [tq*16, tq*16+16)
    int f0 = fc * 64;

    const int tcol = tid & 15, trow = tid >> 4;   // trow 0..7 -> 2 taus each
    unsigned long long acc01[2] = {}, acc23[2] = {};

    #pragma unroll
    for (int kc = 0; kc < 2; kc++) {
        if (kc == 0) {
            const float* Ag = g_A4 + sigma * (64 * 64) + tq * 16;
            #pragma unroll
            for (int li = 0; li < 2; li++) {
                int e = tid + li * 128;
                int k = e >> 2, c4 = (e & 3) << 2;
                float4 v = *reinterpret_cast<const float4*>(Ag + k * 64 + c4);
                *reinterpret_cast<float4*>(&As[k * 20 + c4]) = v;
            }
            #pragma unroll
            for (int li = 0; li < 8; li++) {
                int e = tid + li * 128;
                int r = e >> 4, c4 = (e & 15) << 2;
                float4 v = *reinterpret_cast<const float4*>(
                    g_xg + (r * 32 + sigma) * 256 + f0 + c4);
                *reinterpret_cast<float4*>(&Bs[r * 64 + c4]) = v;
            }
        } else {
            #pragma unroll
            for (int li = 0; li < 2; li++) {
                int e = tid + li * 128;
                int tl = e >> 4, pg = e & 15;
                int q = (tq * 16 + tl) * 32 + sigma;
                float4 v = *reinterpret_cast<const float4*>(g_ctxp + q * 64 + pg * 4);
                float4 u = *reinterpret_cast<const float4*>(g_ctxp2 + q * 64 + pg * 4);
                As[(pg * 4 + 0) * 20 + tl] = v.x + u.x;
                As[(pg * 4 + 1) * 20 + tl] = v.y + u.y;
                As[(pg * 4 + 2) * 20 + tl] = v.z + u.z;
                As[(pg * 4 + 3) * 20 + tl] = v.w + u.w;
            }
            #pragma unroll
            for (int li = 0; li < 8; li++) {
                int e = tid + li * 128;
                int r = e >> 4, c4 = (e & 15) << 2;
                float4 v = *reinterpret_cast<const float4*>(
                    Wg + (256 + r) * 256 + f0 + c4);
                *reinterpret_cast<float4*>(&Bs[r * 64 + c4]) = v;
            }
        }
        __syncthreads();
        #pragma unroll 8
        for (int k = 0; k < 64; k++) {
            float2 av = *reinterpret_cast<const float2*>(&As[k * 20 + trow * 2]);
            ulonglong2 bb = *reinterpret_cast<const ulonglong2*>(&Bs[k * 64 + tcol * 4]);
            unsigned long long ap0 = pack2(av.x);
            unsigned long long ap1 = pack2(av.y);
            ffma2(acc01[0], ap0, bb.x);
            ffma2(acc23[0], ap0, bb.y);
            ffma2(acc01[1], ap1, bb.x);
            ffma2(acc23[1], ap1, bb.y);
        }
        __syncthreads();
    }

    float4 bgv = *reinterpret_cast<const float4*>(bg + f0 + tcol * 4);
    #pragma unroll
    for (int i = 0; i < 2; i++) {
        int tau = tq * 16 + trow * 2 + i;
        int o = (tau * 32 + sigma) * 256 + f0 + tcol * 4;
        float4 cg = *reinterpret_cast<const float4*>(g_ctxg + o);
        float2 v01 = unpack2(acc01[i]);
        float2 v23 = unpack2(acc23[i]);
        float4 r;
        r.x = v01.x + cg.x + 2.f * bgv.x;
        r.y = v01.y + cg.y + 2.f * bgv.y;
        r.z = v23.x + cg.z + 2.f * bgv.z;
        r.w = v23.y + cg.w + 2.f * bgv.w;
        *reinterpret_cast<float4*>(out + o) = r;
    }
}

// ---------------------------------------------------------------------------
extern "C" void kernel_launch(void* const* d_in, const int* in_sizes, int n_in,
                              void* d_out, int out_size) {
    (void)in_sizes; (void)n_in; (void)out_size;
    const float* batch_data = (const float*)d_in[0];
    const float* positions  = (const float*)d_in[1];
    const float* temp       = (const float*)d_in[2];
    const float* Wa         = (const float*)d_in[3];
    const float* ba         = (const float*)d_in[4];
    const float* Wb         = (const float*)d_in[5];
    // d_in[6] = bb : cancels in softmax -> unused
    const float* Wg         = (const float*)d_in[7];
    const float* bg         = (const float*)d_in[8];
    const float* Wpos       = (const float*)d_in[9];
    const float* bpos       = (const float*)d_in[10];
    const float* Wtmp       = (const float*)d_in[11];
    const float* btmp       = (const float*)d_in[12];
    float* out = (float*)d_out;

    cudaFuncSetAttribute((const void*)k1_proj,
                         cudaFuncAttributeMaxDynamicSharedMemorySize, K1_SMEMB);

    k1_proj<<<dim3(64, 7), 128, K1_SMEMB>>>(batch_data, Wa, Wb, Wg, ba, Wtmp,
                                            positions, Wpos, bpos);
    kbig<<<512, 256>>>(temp, Wtmp, btmp);
    k4b_out<<<512, 128>>>(Wg, bg, out);
}